// round 2
// baseline (speedup 1.0000x reference)
#include <cuda_runtime.h>
#include <math.h>

#define L_SEQ 1024
#define NB    16
#define DH    512
#define MROWS (L_SEQ*NB)
#define NCLS  64
#define RCTAS 128

// ---------------- static device scratch (no allocations) ----------------
__device__ __align__(16) float g_bufE[MROWS*DH];   // embedded input
__device__ __align__(16) float g_buf0[MROWS*DH];   // layer0 xs -> layer0 out (in place)
__device__ __align__(16) float g_buf1[MROWS*DH];   // layer1 xs -> layer1 out (in place)
__device__ __align__(16) float g_Wt[DH*DH];        // transposed W_ih[l]
__device__ __align__(16) float g_h[2][NB*DH];      // hidden-state ping-pong
__device__ volatile unsigned g_flagsA[RCTAS];
__device__ volatile unsigned g_flagsB[RCTAS];

__device__ __forceinline__ float* bufsel(int s) {
    return (s == 0) ? g_bufE : ((s == 1) ? g_buf0 : g_buf1);
}

// ---------------- embedding gather + per-replay flag reset ----------------
__global__ void embed_kernel(const int* __restrict__ x, const float* __restrict__ emb) {
    if (blockIdx.x == 0) {           // reset barrier flags for this replay
        g_flagsA[threadIdx.x] = 0u;
        g_flagsB[threadIdx.x] = 0u;
    }
    int m = blockIdx.x;              // m = t*16 + n
    int t = m >> 4, n = m & 15;
    int tok = x[n * L_SEQ + t];
    float4* dst = (float4*)(g_bufE + (size_t)m * DH);
    const float4* src = (const float4*)(emb + (size_t)tok * DH);
    dst[threadIdx.x] = src[threadIdx.x];     // 128 threads * float4 = 512 floats
}

// ---------------- transpose 512x512: g_Wt[k][j] = W[j][k] ----------------
__global__ void transpose_kernel(const float* __restrict__ W) {
    __shared__ float tile[32][33];
    int bx = blockIdx.x * 32, by = blockIdx.y * 32;
    int tx = threadIdx.x, ty = threadIdx.y;
    tile[ty][tx] = W[(by + ty) * DH + bx + tx];
    __syncthreads();
    g_Wt[(bx + ty) * DH + by + tx] = tile[tx][ty];
}

// ---------------- SGEMM: C[M,512] = A[M,512] @ g_Wt + b1 + b2 ----------------
__global__ __launch_bounds__(256) void sgemm_bias(int selA, int selC,
                                                  const float* __restrict__ b1,
                                                  const float* __restrict__ b2) {
    const int N = DH, K = DH;
    const float* A = bufsel(selA);
    float* C = bufsel(selC);
    const float* B = g_Wt;

    __shared__ float As[8][128];
    __shared__ float Bs[8][128];

    int tid  = threadIdx.x;
    int crow = blockIdx.y, ccol = blockIdx.x;
    int trow = tid >> 4, tcol = tid & 15;
    int aRow = tid >> 1, aCol = (tid & 1) * 4;
    int bRow = tid >> 5, bCol = (tid & 31) * 4;

    const float* Ab = A + (size_t)crow * 128 * K;
    const float* Bb = B + ccol * 128;

    float acc[8][8];
#pragma unroll
    for (int i = 0; i < 8; i++)
#pragma unroll
        for (int j = 0; j < 8; j++) acc[i][j] = 0.f;

    for (int k0 = 0; k0 < K; k0 += 8) {
        float4 av = *(const float4*)(Ab + (size_t)aRow * K + k0 + aCol);
        As[aCol + 0][aRow] = av.x;
        As[aCol + 1][aRow] = av.y;
        As[aCol + 2][aRow] = av.z;
        As[aCol + 3][aRow] = av.w;
        *(float4*)(&Bs[bRow][bCol]) = *(const float4*)(Bb + (size_t)(k0 + bRow) * N + bCol);
        __syncthreads();
#pragma unroll
        for (int kk = 0; kk < 8; kk++) {
            float rm[8], rn[8];
#pragma unroll
            for (int i = 0; i < 8; i++) rm[i] = As[kk][trow * 8 + i];
#pragma unroll
            for (int j = 0; j < 8; j++) rn[j] = Bs[kk][tcol * 8 + j];
#pragma unroll
            for (int i = 0; i < 8; i++)
#pragma unroll
                for (int j = 0; j < 8; j++) acc[i][j] += rm[i] * rn[j];
        }
        __syncthreads();
    }

    float bias[8];
#pragma unroll
    for (int j = 0; j < 8; j++) {
        int col = ccol * 128 + tcol * 8 + j;
        bias[j] = b1[col] + b2[col];
    }
#pragma unroll
    for (int i = 0; i < 8; i++) {
        int row = crow * 128 + trow * 8 + i;
        float4* cp = (float4*)(C + (size_t)row * N + ccol * 128 + tcol * 8);
        cp[0] = make_float4(acc[i][0] + bias[0], acc[i][1] + bias[1],
                            acc[i][2] + bias[2], acc[i][3] + bias[3]);
        cp[1] = make_float4(acc[i][4] + bias[4], acc[i][5] + bias[5],
                            acc[i][6] + bias[6], acc[i][7] + bias[7]);
    }
}

// ---------------- recurrence: buf[t] <- tanh(buf[t] + h @ Wh^T) ----------------
// 128 persistent CTAs x 512 threads. CTA owns 4 rows; warp w = batch n=w;
// lane holds Wh[r0..r0+3][lane*16 .. +15] in registers. Flag-array grid barrier.
__global__ __launch_bounds__(512, 1) void rec_kernel(int selBuf,
                                                     const float* __restrict__ Wh,
                                                     int flagSel) {
    float* buf = bufsel(selBuf);
    volatile unsigned* flags = flagSel ? g_flagsB : g_flagsA;
    int tid  = threadIdx.x;
    int n    = tid >> 5;
    int lane = tid & 31;
    int r0   = blockIdx.x * 4;

    float4 w[4][4];
#pragma unroll
    for (int r = 0; r < 4; r++)
#pragma unroll
        for (int j = 0; j < 4; j++)
            w[r][j] = *(const float4*)(Wh + (size_t)(r0 + r) * DH + lane * 16 + j * 4);

    for (int t = 0; t < L_SEQ; t++) {
        if (t > 0) {                      // wait: all h writes of step t-1 visible
            if (tid < RCTAS) {
                while (flags[tid] < (unsigned)t) { }
            }
            __syncthreads();
        }
        float xs = 0.f;
        if (lane < 4) xs = buf[(size_t)(t * NB + n) * DH + r0 + lane];

        float a0 = 0.f, a1 = 0.f, a2 = 0.f, a3 = 0.f;
        if (t > 0) {
            const float4* hp = (const float4*)(g_h[t & 1] + n * DH);
#pragma unroll
            for (int j = 0; j < 4; j++) {
                float4 hv = __ldcg(hp + lane * 4 + j);
                a0 += w[0][j].x * hv.x + w[0][j].y * hv.y + w[0][j].z * hv.z + w[0][j].w * hv.w;
                a1 += w[1][j].x * hv.x + w[1][j].y * hv.y + w[1][j].z * hv.z + w[1][j].w * hv.w;
                a2 += w[2][j].x * hv.x + w[2][j].y * hv.y + w[2][j].z * hv.z + w[2][j].w * hv.w;
                a3 += w[3][j].x * hv.x + w[3][j].y * hv.y + w[3][j].z * hv.z + w[3][j].w * hv.w;
            }
        }
#pragma unroll
        for (int o = 16; o > 0; o >>= 1) {
            a0 += __shfl_xor_sync(0xFFFFFFFFu, a0, o);
            a1 += __shfl_xor_sync(0xFFFFFFFFu, a1, o);
            a2 += __shfl_xor_sync(0xFFFFFFFFu, a2, o);
            a3 += __shfl_xor_sync(0xFFFFFFFFu, a3, o);
        }
        if (lane < 4) {
            float a = (lane == 0) ? a0 : (lane == 1) ? a1 : (lane == 2) ? a2 : a3;
            float v = tanhf(xs + a);
            buf[(size_t)(t * NB + n) * DH + r0 + lane] = v;     // out
            g_h[(t + 1) & 1][n * DH + r0 + lane] = v;           // next h
        }
        if (t < L_SEQ - 1) {
            __syncthreads();
            __threadfence();
            if (tid == 0) flags[blockIdx.x] = (unsigned)(t + 1);
        }
    }
}

// ---------------- head: attention at eos + decoder ----------------
__global__ __launch_bounds__(256) void head_kernel(const int* __restrict__ eos,
                                                   const float* __restrict__ Wc,
                                                   const float* __restrict__ bc,
                                                   const float* __restrict__ Wd,
                                                   const float* __restrict__ bd,
                                                   float* __restrict__ logit) {
    const float* out = g_buf1;            // [t][n][512]
    int b = blockIdx.x;
    int tid = threadIdx.x, warp = tid >> 5, lane = tid & 31;

    __shared__ __align__(16) float cat[2 * DH];   // [0..511]=att_z, [512..1023]=z
    __shared__ __align__(16) float sc[L_SEQ];
    __shared__ __align__(16) float dec[DH];
    __shared__ float red[8];
    __shared__ float s_m, s_denom;

    int e = eos[b];
    int se = (e > 0) ? e : L_SEQ;

    // z = q = out[b, e]
    for (int d = tid; d < DH; d += 256) cat[DH + d] = out[(size_t)(e * NB + b) * DH + d];
    __syncthreads();

    if (e > 0) {
        // scores[s] = <q, out[b,s]>  for s < e
        const float4* qv = (const float4*)(cat + DH);
        for (int s = warp; s < se; s += 8) {
            const float4* row = (const float4*)(out + (size_t)(s * NB + b) * DH);
            float p = 0.f;
            for (int j = lane; j < 128; j += 32) {
                float4 r4 = row[j], q4 = qv[j];
                p += r4.x * q4.x + r4.y * q4.y + r4.z * q4.z + r4.w * q4.w;
            }
#pragma unroll
            for (int o = 16; o > 0; o >>= 1) p += __shfl_xor_sync(0xFFFFFFFFu, p, o);
            if (lane == 0) sc[s] = p;
        }
        __syncthreads();
        // max
        float m = -1e30f;
        for (int s = tid; s < se; s += 256) m = fmaxf(m, sc[s]);
#pragma unroll
        for (int o = 16; o > 0; o >>= 1) m = fmaxf(m, __shfl_xor_sync(0xFFFFFFFFu, m, o));
        if (lane == 0) red[warp] = m;
        __syncthreads();
        if (tid == 0) {
            float mm = red[0];
            for (int i = 1; i < 8; i++) mm = fmaxf(mm, red[i]);
            s_m = mm;
        }
        __syncthreads();
        // exp + sum
        float mm = s_m, sum = 0.f;
        for (int s = tid; s < se; s += 256) {
            float v = expf(sc[s] - mm);
            sc[s] = v;
            sum += v;
        }
#pragma unroll
        for (int o = 16; o > 0; o >>= 1) sum += __shfl_xor_sync(0xFFFFFFFFu, sum, o);
        if (lane == 0) red[warp] = sum;
        __syncthreads();
        if (tid == 0) {
            float ss = 0.f;
            for (int i = 0; i < 8; i++) ss += red[i];
            s_denom = ss;
        }
        __syncthreads();
    }

    // att_z[d] = sum_s att[s] * out[b,s,d]
    float inv = (e > 0) ? (1.f / s_denom) : (1.f / (float)L_SEQ);
    float az0 = 0.f, az1 = 0.f;
    for (int s = 0; s < se; s++) {
        float a = (e > 0) ? sc[s] * inv : inv;
        az0 += a * out[(size_t)(s * NB + b) * DH + tid];
        az1 += a * out[(size_t)(s * NB + b) * DH + tid + 256];
    }
    cat[tid] = az0;
    cat[tid + 256] = az1;
    __syncthreads();

    // dec = concat(att_z, z) @ Wc^T + bc
    const float4* c4 = (const float4*)cat;
    for (int r = warp; r < DH; r += 8) {
        const float4* wr = (const float4*)(Wc + (size_t)r * (2 * DH));
        float p = 0.f;
        for (int j = lane; j < 256; j += 32) {
            float4 a4 = c4[j], w4 = wr[j];
            p += a4.x * w4.x + a4.y * w4.y + a4.z * w4.z + a4.w * w4.w;
        }
#pragma unroll
        for (int o = 16; o > 0; o >>= 1) p += __shfl_xor_sync(0xFFFFFFFFu, p, o);
        if (lane == 0) dec[r] = p + bc[r];
    }
    __syncthreads();

    // logit = dec @ Wd^T + bd
    const float4* d4 = (const float4*)dec;
    for (int c = warp; c < NCLS; c += 8) {
        const float4* wd = (const float4*)(Wd + (size_t)c * DH);
        float p = 0.f;
        for (int j = lane; j < 128; j += 32) {
            float4 a4 = d4[j], w4 = wd[j];
            p += a4.x * w4.x + a4.y * w4.y + a4.z * w4.z + a4.w * w4.w;
        }
#pragma unroll
        for (int o = 16; o > 0; o >>= 1) p += __shfl_xor_sync(0xFFFFFFFFu, p, o);
        if (lane == 0) logit[b * NCLS + c] = p + bd[c];
    }
}

// ---------------- launch ----------------
extern "C" void kernel_launch(void* const* d_in, const int* in_sizes, int n_in,
                              void* d_out, int out_size) {
    const int*   x    = (const int*)d_in[0];
    const int*   eos  = (const int*)d_in[1];
    const float* emb  = (const float*)d_in[2];
    const float* W_ih = (const float*)d_in[3];
    const float* W_hh = (const float*)d_in[4];
    const float* b_ih = (const float*)d_in[5];
    const float* b_hh = (const float*)d_in[6];
    const float* Wc   = (const float*)d_in[7];
    const float* bc   = (const float*)d_in[8];
    const float* Wd   = (const float*)d_in[9];
    const float* bd   = (const float*)d_in[10];
    float* logit = (float*)d_out;

    dim3 tb(32, 32), tg(16, 16);
    dim3 gg(DH / 128, MROWS / 128);

    embed_kernel<<<MROWS, 128>>>(x, emb);

    transpose_kernel<<<tg, tb>>>(W_ih);
    sgemm_bias<<<gg, 256>>>(0, 1, b_ih, b_hh);            // bufE -> buf0
    rec_kernel<<<RCTAS, 512>>>(1, W_hh, 0);               // layer 0 (flagsA)

    transpose_kernel<<<tg, tb>>>(W_ih + DH * DH);
    sgemm_bias<<<gg, 256>>>(1, 2, b_ih + DH, b_hh + DH);  // buf0 -> buf1
    rec_kernel<<<RCTAS, 512>>>(2, W_hh + DH * DH, 1);     // layer 1 (flagsB)

    head_kernel<<<NB, 256>>>(eos, Wc, bc, Wd, bd, logit);
}